// round 12
// baseline (speedup 1.0000x reference)
#include <cuda_runtime.h>
#include <cstdint>

// Unfold (im2col) for x:(B=16, C=128, H=64, W=64), k=3, pad=1.
// out[b, c*9 + p, h*W + w] = x[b, c, h+dh-1, w+dw-1] (zero-padded), p = dh*3+dw.
//
// R11 = R10 (LDG.256/STG.256 + L2 evict_last loads / evict_first stores)
//     + R7's h-pair amortization: 4 row-loads serve 6 row-outputs.
// Per thread: 4x LDG.256, 8 shuffles, 18x STG.256 (each warp-instruction
// covers 1024B contiguous).

#define B_ 16
#define C_ 128
#define H_ 64
#define W_ 64
#define PLANE (H_ * W_)   // 4096

__device__ __forceinline__ void ldg256_el(const float* p, float* f) {
    uint32_t r0, r1, r2, r3, r4, r5, r6, r7;
    asm volatile("ld.global.nc.L2::evict_last.v8.b32 {%0,%1,%2,%3,%4,%5,%6,%7}, [%8];"
                 : "=r"(r0), "=r"(r1), "=r"(r2), "=r"(r3),
                   "=r"(r4), "=r"(r5), "=r"(r6), "=r"(r7)
                 : "l"(p));
    f[0] = __uint_as_float(r0); f[1] = __uint_as_float(r1);
    f[2] = __uint_as_float(r2); f[3] = __uint_as_float(r3);
    f[4] = __uint_as_float(r4); f[5] = __uint_as_float(r5);
    f[6] = __uint_as_float(r6); f[7] = __uint_as_float(r7);
}

__device__ __forceinline__ void stg256_ef(float* p,
    float f0, float f1, float f2, float f3,
    float f4, float f5, float f6, float f7) {
    asm volatile("st.global.L2::evict_first.v8.b32 [%0], {%1,%2,%3,%4,%5,%6,%7,%8};"
                 :: "l"(p),
                    "r"(__float_as_uint(f0)), "r"(__float_as_uint(f1)),
                    "r"(__float_as_uint(f2)), "r"(__float_as_uint(f3)),
                    "r"(__float_as_uint(f4)), "r"(__float_as_uint(f5)),
                    "r"(__float_as_uint(f6)), "r"(__float_as_uint(f7))
                 : "memory");
}

__global__ __launch_bounds__(256) void unfold_kernel(
    const float* __restrict__ x, float* __restrict__ out)
{
    int idx = blockIdx.x * blockDim.x + threadIdx.x;
    // Each thread handles 8 consecutive w of TWO rows: h = 2*hp, 2*hp+1.
    // idx layout: [bc (11b)] [hp (5b)] [wg (3b)]; wg == lane & 7.
    int wg = idx & 7;            // w-group 0..7
    int hp = (idx >> 3) & 31;    // h-pair 0..31
    int bc = idx >> 8;           // b*C + c, 0..2047
    int w0 = wg << 3;            // 0,8,...,56  (32B-aligned in floats)
    int h0 = hp << 1;            // 0,2,...,62

    const float* plane = x + (size_t)bc * PLANE;

    // Front-batch 4 aligned 256-bit loads: rows h0-1 .. h0+2.
    float f[4][8];
#pragma unroll
    for (int r = 0; r < 4; r++) {
        int hh = h0 + r - 1;
        if (hh >= 0 && hh < H_) {
            ldg256_el(plane + hh * W_ + w0, f[r]);
        } else {
#pragma unroll
            for (int c = 0; c < 8; c++) f[r][c] = 0.0f;
        }
    }

    // Edge halo values from neighbor lanes (in-row: wg == lane&7, so the
    // shuffle crosses an h boundary only at wg==0 / wg==7, the pad lanes).
    float e0[4], e5[4];
#pragma unroll
    for (int r = 0; r < 4; r++) {
        float left  = __shfl_up_sync(0xffffffffu, f[r][7], 1);
        float right = __shfl_down_sync(0xffffffffu, f[r][0], 1);
        e0[r] = (wg == 0) ? 0.0f : left;
        e5[r] = (wg == 7) ? 0.0f : right;
    }

    // 18 STG.256: output rows h0+hr (hr=0,1) use source rows f[hr..hr+2].
    float* outp = out + (size_t)bc * 9 * PLANE + h0 * W_ + w0;
#pragma unroll
    for (int hr = 0; hr < 2; hr++) {
        float* obase = outp + hr * W_;
#pragma unroll
        for (int r = 0; r < 3; r++) {
            int s = hr + r;
            float* op = obase + (size_t)(r * 3) * PLANE;
            // dw = -1: window w0-1 .. w0+6
            stg256_ef(op,
                      e0[s],   f[s][0], f[s][1], f[s][2],
                      f[s][3], f[s][4], f[s][5], f[s][6]);
            // dw = 0: window w0 .. w0+7
            stg256_ef(op + PLANE,
                      f[s][0], f[s][1], f[s][2], f[s][3],
                      f[s][4], f[s][5], f[s][6], f[s][7]);
            // dw = +1: window w0+1 .. w0+8
            stg256_ef(op + 2 * PLANE,
                      f[s][1], f[s][2], f[s][3], f[s][4],
                      f[s][5], f[s][6], f[s][7], e5[s]);
        }
    }
}

extern "C" void kernel_launch(void* const* d_in, const int* in_sizes, int n_in,
                              void* d_out, int out_size)
{
    const float* x = (const float*)d_in[0];
    // d_in[1] is the identity "weights" buffer — unused (eye(9) by construction).
    float* out = (float*)d_out;

    const int total  = B_ * C_ * (H_ / 2) * (W_ / 8);  // 524,288 threads
    const int tpb    = 256;
    const int blocks = total / tpb;                    // 2048
    unfold_kernel<<<blocks, tpb>>>(x, out);
}